// round 3
// baseline (speedup 1.0000x reference)
#include <cuda_runtime.h>
#include <cuda_fp16.h>
#include <stdint.h>

#define PN0 8192
#define PN1 16384
#define PN2 8192
#define PD  128
#define NTOT (PN0 + PN1 + PN2)
#define OFF1 ((long)PN0 * PD)
#define OFF2 ((long)(PN0 + PN1) * PD)

#define NUM_TILES 256   // 128 heavy (branch1) + 64 (branch0) + 64 (branch2)
#define GRID 152
#define SMEM_BASE 1024
#define STAGE_BYTES 49152          // A_hi 16K | A_lo 16K | B 16K
#define DYN_SMEM (SMEM_BASE + 2 * STAGE_BYTES)

// x^T in fp16: g_bt[branch_off + j*N + k] = x[k][j]
__device__ __half g_bt[(long)NTOT * PD];
__device__ __half g_w16[3 * PD * PD];
__device__ unsigned g_ctr;

#define SWZ128(o) ((uint32_t)(o) ^ ((((uint32_t)(o)) >> 3) & 0x70))

__device__ __forceinline__ uint32_t smem_to_u32(const void* p) {
    uint32_t a;
    asm("{ .reg .u64 t; cvta.to.shared.u64 t, %1; cvt.u32.u64 %0, t; }" : "=r"(a) : "l"(p));
    return a;
}
__device__ __forceinline__ void ldsm_x4(uint32_t* r, uint32_t addr) {
    asm volatile("ldmatrix.sync.aligned.m8n8.x4.shared.b16 {%0,%1,%2,%3}, [%4];"
                 : "=r"(r[0]), "=r"(r[1]), "=r"(r[2]), "=r"(r[3]) : "r"(addr));
}
__device__ __forceinline__ void mma16816(float* c, const uint32_t* a, const uint32_t* b) {
    asm volatile("mma.sync.aligned.m16n8k16.row.col.f32.f16.f16.f32 "
                 "{%0,%1,%2,%3}, {%4,%5,%6,%7}, {%8,%9}, {%0,%1,%2,%3};"
                 : "+f"(c[0]), "+f"(c[1]), "+f"(c[2]), "+f"(c[3])
                 : "r"(a[0]), "r"(a[1]), "r"(a[2]), "r"(a[3]), "r"(b[0]), "r"(b[1]));
}
__device__ __forceinline__ uint32_t pack_h2(__half a, __half b) {
    __half2 t = __halves2half2(a, b);
    return *reinterpret_cast<uint32_t*>(&t);
}

// One 128x128x64 MMA block, 2 passes (A_hi*B + A_lo*B), frags from swizzled smem.
// sAhi/sAlo: [128 rows][64 k] fp16, sB: [128 n][64 k] fp16 (all 128B rows, SW128).
__device__ __forceinline__ void mma_block(float acc[2][8][4],
                                          uint32_t sAhi, uint32_t sAlo, uint32_t sB,
                                          int mrow, int ncol, int l) {
    const uint32_t a_lane = (uint32_t)((l & 15) * 128 + (l >> 4) * 16);
    const uint32_t b_lane = (uint32_t)(((l & 7) + ((l >> 4) & 1) * 8) * 128 + ((l >> 3) & 1) * 16);
    #pragma unroll
    for (int kb = 0; kb < 4; kb++) {
        uint32_t ah[2][4], al[2][4], bf[4][4];
        #pragma unroll
        for (int mi = 0; mi < 2; mi++) {
            uint32_t off = (uint32_t)((mrow + mi * 16) * 128 + kb * 32) + a_lane;
            ldsm_x4(ah[mi], sAhi + SWZ128(off));
            ldsm_x4(al[mi], sAlo + SWZ128(off));
        }
        #pragma unroll
        for (int g = 0; g < 4; g++) {
            uint32_t off = (uint32_t)((ncol + g * 16) * 128 + kb * 32) + b_lane;
            ldsm_x4(bf[g], sB + SWZ128(off));
        }
        #pragma unroll
        for (int mi = 0; mi < 2; mi++)
            #pragma unroll
            for (int nb = 0; nb < 8; nb++) {
                const uint32_t* bp = &bf[nb >> 1][(nb & 1) * 2];
                mma16816(acc[mi][nb], ah[mi], bp);
                mma16816(acc[mi][nb], al[mi], bp);
            }
    }
}

// ------------------------------------------------------------------ prepasses
// x [N][128] fp32 -> g_bt[off + j*N + k] fp16
__global__ void prep_bt(const float* __restrict__ X, long off, int N) {
    __shared__ float tile[32][33];
    int k0 = blockIdx.x * 32, j0 = blockIdx.y * 32;
    int tx = threadIdx.x, ty = threadIdx.y;  // (32, 8)
    #pragma unroll
    for (int i = 0; i < 32; i += 8)
        tile[ty + i][tx] = X[(long)(k0 + ty + i) * PD + j0 + tx];
    __syncthreads();
    #pragma unroll
    for (int i = 0; i < 32; i += 8) {
        long j = j0 + ty + i, k = k0 + tx;
        g_bt[off + j * N + k] = __float2half_rn(tile[tx][ty + i]);
    }
}
// W fp32 -> fp16, and reset the tile counter (runs every graph replay)
__global__ void prep_aux(const float* __restrict__ W0, const float* __restrict__ W1,
                         const float* __restrict__ W2) {
    int i = blockIdx.x * blockDim.x + threadIdx.x;
    if (i == 0) g_ctr = 0u;
    if (i < PD * PD) {
        g_w16[i]              = __float2half_rn(W0[i]);
        g_w16[PD * PD + i]    = __float2half_rn(W1[i]);
        g_w16[2 * PD * PD + i] = __float2half_rn(W2[i]);
    }
}

// ------------------------------------------------------------------ main
__global__ void __launch_bounds__(256, 1)
scn_main(const float* __restrict__ x0, const float* __restrict__ x1, const float* __restrict__ x2,
         const float* __restrict__ L0, const float* __restrict__ L1, const float* __restrict__ L2,
         const float* __restrict__ bv0, const float* __restrict__ bv1, const float* __restrict__ bv2,
         float* __restrict__ out)
{
    extern __shared__ char smem[];
    const uint32_t sbase = smem_to_u32(smem);
    const int t = threadIdx.x;
    const int l = t & 31, w = t >> 5;
    const int mrow = (w & 3) * 32, ncol = (w >> 2) * 64;
    const int ar = t >> 1, ah2 = t & 1;       // loader row / half
    volatile int* sidx = (volatile int*)smem;

    for (;;) {
        if (t == 0) *sidx = (int)atomicAdd(&g_ctr, 1u);
        __syncthreads();
        const int idx = *sidx;
        if (idx >= NUM_TILES) break;

        const float *L, *X, *bvec;
        const __half *bt, *wv;
        float* o;
        long N; int tile;
        if (idx < 128) {                 // branch 1 (heavy) first
            L = L1; X = x1; bvec = bv1; N = PN1; tile = idx;
            bt = g_bt + OFF1; wv = g_w16 + PD * PD; o = out + OFF1;
        } else if (idx < 192) {          // branch 0
            L = L0; X = x0; bvec = bv0; N = PN0; tile = idx - 128;
            bt = g_bt; wv = g_w16; o = out;
        } else {                         // branch 2
            L = L2; X = x2; bvec = bv2; N = PN2; tile = idx - 192;
            bt = g_bt + OFF2; wv = g_w16 + 2 * PD * PD; o = out + OFF2;
        }
        const long m0 = (long)tile * 128;
        const int KI = (int)(N >> 6);

        const float* Ap = L + (m0 + ar) * N + ah2 * 32;
        const __half* Bp = bt + (long)ar * N + ah2 * 32;

        float acc[2][8][4];
        #pragma unroll
        for (int mi = 0; mi < 2; mi++)
            #pragma unroll
            for (int nb = 0; nb < 8; nb++)
                #pragma unroll
                for (int i = 0; i < 4; i++) acc[mi][nb][i] = 0.f;

        float4 av[8]; uint4 bvx[4];
        // prologue: fetch K-step 0
        #pragma unroll
        for (int i = 0; i < 8; i++) av[i] = __ldcs((const float4*)Ap + i);
        #pragma unroll
        for (int i = 0; i < 4; i++) bvx[i] = *(const uint4*)(Bp + i * 8);
        {   // STS stage 0
            char* dA = smem + SMEM_BASE;
            #pragma unroll
            for (int i = 0; i < 4; i++) {
                float4 v0 = av[2 * i], v1 = av[2 * i + 1];
                __half h0 = __float2half_rn(v0.x), h1 = __float2half_rn(v0.y);
                __half h2v = __float2half_rn(v0.z), h3 = __float2half_rn(v0.w);
                __half h4 = __float2half_rn(v1.x), h5 = __float2half_rn(v1.y);
                __half h6 = __float2half_rn(v1.z), h7 = __float2half_rn(v1.w);
                uint4 H = { pack_h2(h0, h1), pack_h2(h2v, h3), pack_h2(h4, h5), pack_h2(h6, h7) };
                uint4 Lo = {
                    pack_h2(__float2half_rn(v0.x - __half2float(h0)), __float2half_rn(v0.y - __half2float(h1))),
                    pack_h2(__float2half_rn(v0.z - __half2float(h2v)), __float2half_rn(v0.w - __half2float(h3))),
                    pack_h2(__float2half_rn(v1.x - __half2float(h4)), __float2half_rn(v1.y - __half2float(h5))),
                    pack_h2(__float2half_rn(v1.z - __half2float(h6)), __float2half_rn(v1.w - __half2float(h7))) };
                uint32_t sw = SWZ128(ar * 128 + ah2 * 64 + i * 16);
                *(uint4*)(dA + sw) = H;
                *(uint4*)(dA + 16384 + sw) = Lo;
                *(uint4*)(dA + 32768 + sw) = bvx[i];
            }
        }
        __syncthreads();

        for (int k = 0; k < KI; k++) {
            const int s = k & 1;
            const bool pf = (k + 1 < KI);
            if (pf) {
                const float* ap = Ap + (long)(k + 1) * 64;
                const __half* bp = Bp + (long)(k + 1) * 64;
                #pragma unroll
                for (int i = 0; i < 8; i++) av[i] = __ldcs((const float4*)ap + i);
                #pragma unroll
                for (int i = 0; i < 4; i++) bvx[i] = *(const uint4*)(bp + i * 8);
            }
            const uint32_t sA = sbase + SMEM_BASE + s * STAGE_BYTES;
            mma_block(acc, sA, sA + 16384, sA + 32768, mrow, ncol, l);
            if (pf) {
                char* dA = smem + SMEM_BASE + (s ^ 1) * STAGE_BYTES;
                #pragma unroll
                for (int i = 0; i < 4; i++) {
                    float4 v0 = av[2 * i], v1 = av[2 * i + 1];
                    __half h0 = __float2half_rn(v0.x), h1 = __float2half_rn(v0.y);
                    __half h2v = __float2half_rn(v0.z), h3 = __float2half_rn(v0.w);
                    __half h4 = __float2half_rn(v1.x), h5 = __float2half_rn(v1.y);
                    __half h6 = __float2half_rn(v1.z), h7 = __float2half_rn(v1.w);
                    uint4 H = { pack_h2(h0, h1), pack_h2(h2v, h3), pack_h2(h4, h5), pack_h2(h6, h7) };
                    uint4 Lo = {
                        pack_h2(__float2half_rn(v0.x - __half2float(h0)), __float2half_rn(v0.y - __half2float(h1))),
                        pack_h2(__float2half_rn(v0.z - __half2float(h2v)), __float2half_rn(v0.w - __half2float(h3))),
                        pack_h2(__float2half_rn(v1.x - __half2float(h4)), __float2half_rn(v1.y - __half2float(h5))),
                        pack_h2(__float2half_rn(v1.z - __half2float(h6)), __float2half_rn(v1.w - __half2float(h7))) };
                    uint32_t sw = SWZ128(ar * 128 + ah2 * 64 + i * 16);
                    *(uint4*)(dA + sw) = H;
                    *(uint4*)(dA + 16384 + sw) = Lo;
                    *(uint4*)(dA + 32768 + sw) = bvx[i];
                }
            }
            __syncthreads();
        }

        // ---- epilogue: Y = acc + x -> fp16 hi/lo panels; W -> fp16 panel ----
        char* yh = smem + SMEM_BASE;            // 2 panels x 16K  (k 0-63 | 64-127)
        char* yl = smem + SMEM_BASE + 32768;
        char* wp = smem + SMEM_BASE + 65536;
        #pragma unroll
        for (int mi = 0; mi < 2; mi++)
            #pragma unroll
            for (int nb = 0; nb < 8; nb++) {
                int row = mrow + mi * 16 + (l >> 2);
                int col = ncol + nb * 8 + (l & 3) * 2;
                float2 xv0 = __ldg((const float2*)(X + (m0 + row) * PD + col));
                float2 xv1 = __ldg((const float2*)(X + (m0 + row + 8) * PD + col));
                float y0 = acc[mi][nb][0] + xv0.x, y1 = acc[mi][nb][1] + xv0.y;
                float y2 = acc[mi][nb][2] + xv1.x, y3 = acc[mi][nb][3] + xv1.y;
                __half q0 = __float2half_rn(y0), q1 = __float2half_rn(y1);
                __half q2 = __float2half_rn(y2), q3 = __float2half_rn(y3);
                int p = (col >> 6) * 16384, cb = (col & 63) * 2;
                uint32_t sw0 = SWZ128(row * 128 + cb), sw1 = SWZ128((row + 8) * 128 + cb);
                *(uint32_t*)(yh + p + sw0) = pack_h2(q0, q1);
                *(uint32_t*)(yh + p + sw1) = pack_h2(q2, q3);
                *(uint32_t*)(yl + p + sw0) = pack_h2(__float2half_rn(y0 - __half2float(q0)),
                                                     __float2half_rn(y1 - __half2float(q1)));
                *(uint32_t*)(yl + p + sw1) = pack_h2(__float2half_rn(y2 - __half2float(q2)),
                                                     __float2half_rn(y3 - __half2float(q3)));
            }
        {   // stage W: row n=t>>1, panel=t&1 (64 halfs = 128B)
            const __half* wsrc = wv + (t >> 1) * PD + (t & 1) * 64;
            char* wdst = wp + (t & 1) * 16384;
            #pragma unroll
            for (int i = 0; i < 8; i++)
                *(uint4*)(wdst + SWZ128((t >> 1) * 128 + i * 16)) = *(const uint4*)(wsrc + i * 8);
        }
        __syncthreads();

        // ---- GEMM2: Z = relu(Y @ W^T + b) via HMMA, 2 k-panels x 2 passes ----
        #pragma unroll
        for (int mi = 0; mi < 2; mi++)
            #pragma unroll
            for (int nb = 0; nb < 8; nb++)
                #pragma unroll
                for (int i = 0; i < 4; i++) acc[mi][nb][i] = 0.f;
        mma_block(acc, sbase + SMEM_BASE,         sbase + SMEM_BASE + 32768,
                       sbase + SMEM_BASE + 65536, mrow, ncol, l);
        mma_block(acc, sbase + SMEM_BASE + 16384, sbase + SMEM_BASE + 49152,
                       sbase + SMEM_BASE + 81920, mrow, ncol, l);

        #pragma unroll
        for (int mi = 0; mi < 2; mi++)
            #pragma unroll
            for (int nb = 0; nb < 8; nb++) {
                int row = mrow + mi * 16 + (l >> 2);
                int col = ncol + nb * 8 + (l & 3) * 2;
                float2 bb = __ldg((const float2*)(bvec + col));
                float2 z0, z1;
                z0.x = fmaxf(acc[mi][nb][0] + bb.x, 0.f);
                z0.y = fmaxf(acc[mi][nb][1] + bb.y, 0.f);
                z1.x = fmaxf(acc[mi][nb][2] + bb.x, 0.f);
                z1.y = fmaxf(acc[mi][nb][3] + bb.y, 0.f);
                *(float2*)(o + (m0 + row) * PD + col) = z0;
                *(float2*)(o + (m0 + row + 8) * PD + col) = z1;
            }
        __syncthreads();   // protect smem + sidx before next tile
    }
}

// ------------------------------------------------------------------ launch
extern "C" void kernel_launch(void* const* d_in, const int* in_sizes, int n_in,
                              void* d_out, int out_size) {
    const float* x0 = (const float*)d_in[0];
    const float* x1 = (const float*)d_in[1];
    const float* x2 = (const float*)d_in[2];
    const float* L0 = (const float*)d_in[3];
    const float* L1 = (const float*)d_in[4];
    const float* L2 = (const float*)d_in[5];
    const float* W0 = (const float*)d_in[6];
    const float* b0 = (const float*)d_in[7];
    const float* W1 = (const float*)d_in[8];
    const float* b1 = (const float*)d_in[9];
    const float* W2 = (const float*)d_in[10];
    const float* b2 = (const float*)d_in[11];
    float* out = (float*)d_out;

    cudaFuncSetAttribute(scn_main, cudaFuncAttributeMaxDynamicSharedMemorySize, DYN_SMEM);

    dim3 tb(32, 8);
    prep_bt<<<dim3(PN0 / 32, PD / 32), tb>>>(x0, 0L, PN0);
    prep_bt<<<dim3(PN1 / 32, PD / 32), tb>>>(x1, OFF1, PN1);
    prep_bt<<<dim3(PN2 / 32, PD / 32), tb>>>(x2, OFF2, PN2);
    prep_aux<<<64, 256>>>(W0, W1, W2);

    scn_main<<<GRID, 256, DYN_SMEM>>>(x0, x1, x2, L0, L1, L2, b0, b1, b2, out);
}